// round 7
// baseline (speedup 1.0000x reference)
#include <cuda_runtime.h>
#include <cuda_bf16.h>
#include <cstdint>

#define D 784
#define H 1024
#define BATCH 1024
#define THREADS 512
#define R 7                      // batch rows per CTA
#define NCTAS 147                // 147*7 = 1029 >= 1024
#define CHUNK 49                 // 784 = 16 * 49
#define NCHUNKS (D / CHUNK)
#define SX_BYTES (D * 8 * 4)                   // sx8[D][8]
#define SP_BYTES (CHUNK * 16 * 8 * 4 * 4)      // sp[CHUNK][16][8][4]
#define SMEM_BYTES (SX_BYTES + SP_BYTES)       // 125440

// Scratch (no allocations allowed): transposed W and fused bias.
__device__ float g_WT[D * H];   // g_WT[i*H + h] = W[h*D + i]
__device__ float g_bias[D];     // bias[i] = b[i] + 0.5 * sum_h V[i,h]

// Two tanh evaluations in ONE MUFU op via f16x2.
__device__ __forceinline__ void tanh2(float a, float b, float& ta, float& tb) {
    uint32_t pk, tk;
    asm("cvt.rn.f16x2.f32 %0, %1, %2;" : "=r"(pk) : "f"(b), "f"(a)); // lo=a, hi=b
    asm("tanh.approx.f16x2 %0, %1;" : "=r"(tk) : "r"(pk));
    asm("{\n\t.reg .b16 l, h;\n\t"
        "mov.b32 {l, h}, %2;\n\t"
        "cvt.f32.f16 %0, l;\n\t"
        "cvt.f32.f16 %1, h;\n\t}"
        : "=f"(ta), "=f"(tb) : "r"(tk));
}

// Transmit-select fold: combine partials a (slot bit=0) and b (slot bit=1)
// across lane pairs (lane ^ m). Result: lanes with bit=0 hold pair-sum of a,
// lanes with bit=1 hold pair-sum of b. 1 SHFL + 2 SEL + 1 ADD.
__device__ __forceinline__ float fold(float a, float b, bool hi, int m) {
    float snd  = hi ? a : b;
    float kept = hi ? b : a;
    float rcv = __shfl_xor_sync(0xffffffffu, snd, m);
    return kept + rcv;
}

// ---------------------------------------------------------------------------
// Fused prep: blockIdx.y < 32 -> tiled transpose W[H,D] -> g_WT[D,H]
//             blockIdx.y == 32 -> bias[i] = b[i] + 0.5 * sum_h V[i,h]
// ---------------------------------------------------------------------------
__global__ void prep_kernel(const float* __restrict__ W,
                            const float* __restrict__ V,
                            const float* __restrict__ bvec) {
    if (blockIdx.y < 32) {
        __shared__ float tile[32][33];
        int ix = blockIdx.x * 32 + threadIdx.x;   // D index
        int iy = blockIdx.y * 32 + threadIdx.y;   // H index
        #pragma unroll
        for (int j = 0; j < 32; j += 8) {
            int y = iy + j;
            if (ix < D && y < H)
                tile[threadIdx.y + j][threadIdx.x] = W[y * D + ix];
        }
        __syncthreads();
        int ox = blockIdx.y * 32 + threadIdx.x;   // H index
        int oy = blockIdx.x * 32 + threadIdx.y;   // D index
        #pragma unroll
        for (int j = 0; j < 32; j += 8) {
            int y = oy + j;
            if (ox < H && y < D)
                g_WT[y * H + ox] = tile[threadIdx.x][threadIdx.y + j];
        }
    } else {
        int lane = threadIdx.x;
        int w    = threadIdx.y;
        #pragma unroll
        for (int k = 0; k < 4; k++) {
            int i = blockIdx.x * 32 + w * 4 + k;
            if (i >= D) continue;
            float s = 0.0f;
            #pragma unroll
            for (int j = 0; j < H / 32; j++) s += V[i * H + j * 32 + lane];
            #pragma unroll
            for (int o = 16; o > 0; o >>= 1)
                s += __shfl_xor_sync(0xffffffffu, s, o);
            if (lane == 0) g_bias[i] = bvec[i] + 0.5f * s;
        }
    }
}

// ---------------------------------------------------------------------------
// Main: one CTA per 7 batch rows; 512 threads (16 warps), 2 h per lane.
// A = a/2 in float2 registers (7 per thread). Per step per warp:
//   LDG.64 v + LDG.64 w; 2x LDS.128 xs; 7 tanh2; 14 dot FMA; 14 acc FMA;
//   3-level transmit-select fold (7 SHFL, 28 instr); full-lane STS (1 wf).
// Remaining 4-lane sums + 16-warp sums deferred to the chunk epilogue.
// ---------------------------------------------------------------------------
__global__ void __launch_bounds__(THREADS)
nade_main(const float* __restrict__ pixels,
          const float* __restrict__ c,
          const float* __restrict__ V,
          float* __restrict__ out) {
    extern __shared__ char smem_raw[];
    float* sx8 = reinterpret_cast<float*>(smem_raw);              // [D][8]
    float* sp  = reinterpret_cast<float*>(smem_raw + SX_BYTES);   // [CHUNK][16][8][4]

    const int b0   = blockIdx.x * R;
    const int t    = threadIdx.x;
    const int lane = t & 31;
    const int wid  = t >> 5;

    for (int i = t; i < D; i += THREADS) {
        #pragma unroll
        for (int r = 0; r < R; r++) {
            int br = min(b0 + r, BATCH - 1);
            sx8[i * 8 + r] = 0.5f * pixels[br * D + i];
        }
        sx8[i * 8 + 7] = 0.0f;
    }

    float2 A[R];
    {
        float2 cc = reinterpret_cast<const float2*>(c)[t];
        cc.x *= 0.5f; cc.y *= 0.5f;
        #pragma unroll
        for (int r = 0; r < R; r++) A[r] = cc;
    }
    __syncthreads();

    const bool hi16 = (lane & 16) != 0;
    const bool hi8  = (lane & 8)  != 0;
    const bool hi4  = (lane & 4)  != 0;
    // Row held by this lane after the 3 fold levels.
    const int rowmap = ((lane >> 4) & 1) | (((lane >> 3) & 1) << 1)
                     | (((lane >> 2) & 1) << 2);
    // STS target: permutation of 32 consecutive floats -> conflict-free.
    const int sts_off = rowmap * 4 + (lane & 3);

    const float2* __restrict__ V2 = reinterpret_cast<const float2*>(V);
    const float2* __restrict__ W2 = reinterpret_cast<const float2*>(g_WT);

    for (int ch = 0; ch < NCHUNKS; ch++) {
        const int ibase = ch * CHUNK;

        #pragma unroll 2
        for (int il = 0; il < CHUNK; il++) {
            const int i = ibase + il;
            const int roff = i * (H / 2) + t;
            float2 v = V2[roff];
            float2 w = W2[roff];
            const float4* xs4 = reinterpret_cast<const float4*>(&sx8[i * 8]);
            float4 x03 = xs4[0];
            float4 x47 = xs4[1];

            float p0, p1, p2, p3, p4, p5, p6;
            {
                float t0, t1;
                tanh2(A[0].x, A[0].y, t0, t1); p0 = fmaf(v.y, t1, v.x * t0);
                tanh2(A[1].x, A[1].y, t0, t1); p1 = fmaf(v.y, t1, v.x * t0);
                tanh2(A[2].x, A[2].y, t0, t1); p2 = fmaf(v.y, t1, v.x * t0);
                tanh2(A[3].x, A[3].y, t0, t1); p3 = fmaf(v.y, t1, v.x * t0);
                tanh2(A[4].x, A[4].y, t0, t1); p4 = fmaf(v.y, t1, v.x * t0);
                tanh2(A[5].x, A[5].y, t0, t1); p5 = fmaf(v.y, t1, v.x * t0);
                tanh2(A[6].x, A[6].y, t0, t1); p6 = fmaf(v.y, t1, v.x * t0);
            }

            A[0].x = fmaf(w.x, x03.x, A[0].x);
            A[0].y = fmaf(w.y, x03.x, A[0].y);
            A[1].x = fmaf(w.x, x03.y, A[1].x);
            A[1].y = fmaf(w.y, x03.y, A[1].y);
            A[2].x = fmaf(w.x, x03.z, A[2].x);
            A[2].y = fmaf(w.y, x03.z, A[2].y);
            A[3].x = fmaf(w.x, x03.w, A[3].x);
            A[3].y = fmaf(w.y, x03.w, A[3].y);
            A[4].x = fmaf(w.x, x47.x, A[4].x);
            A[4].y = fmaf(w.y, x47.x, A[4].y);
            A[5].x = fmaf(w.x, x47.y, A[5].x);
            A[5].y = fmaf(w.y, x47.y, A[5].y);
            A[6].x = fmaf(w.x, x47.z, A[6].x);
            A[6].y = fmaf(w.y, x47.z, A[6].y);

            // 3-level transmit-select fold: 7 SHFLs for 8 slots (7 rows + 0).
            float q01 = fold(p0, p1,   hi16, 16);
            float q23 = fold(p2, p3,   hi16, 16);
            float q45 = fold(p4, p5,   hi16, 16);
            float q67 = fold(p6, 0.0f, hi16, 16);
            float q03 = fold(q01, q23, hi8, 8);
            float q47 = fold(q45, q67, hi8, 8);
            float qq  = fold(q03, q47, hi4, 4);

            // Every lane stores its 4-lane partial: 1 conflict-free wavefront.
            sp[(il * 16 + wid) * 32 + sts_off] = qq;
        }

        __syncthreads();

        // Epilogue: for each (step, row) sum 16 warps x 4 lane-partials.
        for (int o = t; o < CHUNK * R; o += THREADS) {
            int il = o / R, r = o % R;
            float s = 0.0f;
            #pragma unroll
            for (int wi = 0; wi < 16; wi++) {
                const float4 q = *reinterpret_cast<const float4*>(
                    &sp[(il * 16 + wi) * 32 + r * 4]);
                s += (q.x + q.y) + (q.z + q.w);
            }
            int i = ibase + il;
            int b = b0 + r;
            if (b < BATCH) out[b * D + i] = fmaf(0.5f, s, g_bias[i]);
        }

        __syncthreads();
    }
}

// ---------------------------------------------------------------------------
extern "C" void kernel_launch(void* const* d_in, const int* in_sizes, int n_in,
                              void* d_out, int out_size) {
    const float* pixels = (const float*)d_in[0];   // [1024, 784]
    const float* W      = (const float*)d_in[1];   // [1024, 784]
    const float* c      = (const float*)d_in[2];   // [1024]
    const float* V      = (const float*)d_in[3];   // [784, 1024]
    const float* bvec   = (const float*)d_in[4];   // [784]
    float* out          = (float*)d_out;           // [1024, 784]

    cudaFuncSetAttribute(nade_main, cudaFuncAttributeMaxDynamicSharedMemorySize,
                         SMEM_BYTES);
    cudaFuncSetAttribute(nade_main, cudaFuncAttributePreferredSharedMemoryCarveout,
                         100);

    prep_kernel<<<dim3(25, 33), dim3(32, 8)>>>(W, V, bvec);
    nade_main<<<NCTAS, THREADS, SMEM_BYTES>>>(pixels, c, V, out);
}

// round 8
// speedup vs baseline: 1.0481x; 1.0481x over previous
#include <cuda_runtime.h>
#include <cuda_bf16.h>
#include <cstdint>

#define D 784
#define H 1024
#define BATCH 1024
#define THREADS 512
#define R 7                      // batch rows per CTA
#define NCTAS 147                // 147*7 = 1029 >= 1024
#define CHUNK 98                 // 784 = 8 * 98 (EVEN - keeps unroll-2 pipelining)
#define NCHUNKS (D / CHUNK)
#define SX_BYTES (D * 8 * 4)                 // sx8[D][8]
#define SP_BYTES (CHUNK * 16 * 8 * 4)        // sp[CHUNK][16][8]
#define SMEM_BYTES (SX_BYTES + SP_BYTES)     // 75264

// Scratch (no allocations allowed).
__device__ float4 g_VW[D * (H / 2)];  // g_VW[i*512 + t] = (V[i,2t], V[i,2t+1], W[2t,i], W[2t+1,i])
__device__ float  g_bias[D];          // bias[i] = b[i] + 0.5 * sum_h V[i,h]

// Two tanh evaluations in ONE MUFU op via f16x2.
__device__ __forceinline__ void tanh2(float a, float b, float& ta, float& tb) {
    uint32_t pk, tk;
    asm("cvt.rn.f16x2.f32 %0, %1, %2;" : "=r"(pk) : "f"(b), "f"(a)); // lo=a, hi=b
    asm("tanh.approx.f16x2 %0, %1;" : "=r"(tk) : "r"(pk));
    asm("{\n\t.reg .b16 l, h;\n\t"
        "mov.b32 {l, h}, %2;\n\t"
        "cvt.f32.f16 %0, l;\n\t"
        "cvt.f32.f16 %1, h;\n\t}"
        : "=f"(ta), "=f"(tb) : "r"(tk));
}

// Transmit-select fold: 1 SHFL + 2 SEL + 1 ADD combines two slot-partials
// across lane pairs (lane ^ m). Lanes with bit clear end up holding slot-a's
// pair sum; lanes with bit set hold slot-b's.
__device__ __forceinline__ float fold(float a, float b, bool hi, int m) {
    float snd  = hi ? a : b;
    float kept = hi ? b : a;
    float rcv = __shfl_xor_sync(0xffffffffu, snd, m);
    return kept + rcv;
}

// ---------------------------------------------------------------------------
// Fused prep: blockIdx.y < 32 -> build interleaved g_VW tile (transpose W via
//                                smem tile, merge with V)
//             blockIdx.y == 32 -> bias[i] = b[i] + 0.5 * sum_h V[i,h]
// ---------------------------------------------------------------------------
__global__ void prep_kernel(const float* __restrict__ W,
                            const float* __restrict__ V,
                            const float* __restrict__ bvec) {
    if (blockIdx.y < 32) {
        __shared__ float tile[32][33];
        const int i0 = blockIdx.x * 32;
        const int h0 = blockIdx.y * 32;
        const int tx = threadIdx.x, ty = threadIdx.y;
        // Load W[h0..h0+32)[i0..i0+32) coalesced over i.
        #pragma unroll
        for (int j = 0; j < 32; j += 8) {
            int ii = i0 + tx;
            if (ii < D) tile[ty + j][tx] = W[(h0 + ty + j) * D + ii];
        }
        __syncthreads();
        // Write 16 float4 per i-row (tcol = h0/2 + tx for tx < 16).
        #pragma unroll
        for (int j = 0; j < 32; j += 8) {
            int i = i0 + ty + j;
            if (i < D && tx < 16) {
                int tcol = h0 / 2 + tx;
                float2 v2 = reinterpret_cast<const float2*>(V)[i * (H / 2) + tcol];
                g_VW[i * (H / 2) + tcol] =
                    make_float4(v2.x, v2.y, tile[2 * tx][i - i0], tile[2 * tx + 1][i - i0]);
            }
        }
    } else {
        int lane = threadIdx.x;
        int w    = threadIdx.y;
        #pragma unroll
        for (int k = 0; k < 4; k++) {
            int i = blockIdx.x * 32 + w * 4 + k;
            if (i >= D) continue;
            float s = 0.0f;
            #pragma unroll
            for (int j = 0; j < H / 32; j++) s += V[i * H + j * 32 + lane];
            #pragma unroll
            for (int o = 16; o > 0; o >>= 1)
                s += __shfl_xor_sync(0xffffffffu, s, o);
            if (lane == 0) g_bias[i] = bvec[i] + 0.5f * s;
        }
    }
}

// ---------------------------------------------------------------------------
// Main: one CTA per 7 batch rows; 512 threads (16 warps), 2 h per lane.
// Per step per warp: 1x LDG.128 (v+w interleaved); 2x LDS.128 xs (broadcast);
// 7 tanh2; 14 dot FMA; 14 acc FMA; 9-SHFL transmit-select fold; 1 pred STS.
// Partials deferred per 98-step chunk, then cross-warp reduced + stored.
// ---------------------------------------------------------------------------
__global__ void __launch_bounds__(THREADS)
nade_main(const float* __restrict__ pixels,
          const float* __restrict__ c,
          float* __restrict__ out) {
    extern __shared__ char smem_raw[];
    float* sx8 = reinterpret_cast<float*>(smem_raw);              // [D][8]
    float* sp  = reinterpret_cast<float*>(smem_raw + SX_BYTES);   // [CHUNK][16][8]

    const int b0   = blockIdx.x * R;
    const int t    = threadIdx.x;
    const int lane = t & 31;
    const int wid  = t >> 5;

    for (int i = t; i < D; i += THREADS) {
        #pragma unroll
        for (int r = 0; r < R; r++) {
            int br = min(b0 + r, BATCH - 1);
            sx8[i * 8 + r] = 0.5f * pixels[br * D + i];
        }
        sx8[i * 8 + 7] = 0.0f;
    }

    float2 A[R];
    {
        float2 cc = reinterpret_cast<const float2*>(c)[t];
        cc.x *= 0.5f; cc.y *= 0.5f;
        #pragma unroll
        for (int r = 0; r < R; r++) A[r] = cc;
    }
    __syncthreads();

    const bool hi16 = (lane & 16) != 0;
    const bool hi8  = (lane & 8)  != 0;
    const bool hi4  = (lane & 4)  != 0;
    // Slot held by this lane after the 3 fold levels.
    const int rowmap = ((lane >> 4) & 1) | (((lane >> 3) & 1) << 1)
                     | (((lane >> 2) & 1) << 2);
    const bool is_head = (lane & 3) == 0;

    const float4* __restrict__ VW4 = g_VW;

    for (int ch = 0; ch < NCHUNKS; ch++) {
        const int ibase = ch * CHUNK;

        #pragma unroll 2
        for (int il = 0; il < CHUNK; il++) {
            const int i = ibase + il;
            float4 vw = VW4[i * (H / 2) + t];
            const float4* xs4 = reinterpret_cast<const float4*>(&sx8[i * 8]);
            float4 x03 = xs4[0];
            float4 x47 = xs4[1];

            float p0, p1, p2, p3, p4, p5, p6;
            {
                float t0, t1;
                tanh2(A[0].x, A[0].y, t0, t1); p0 = fmaf(vw.y, t1, vw.x * t0);
                tanh2(A[1].x, A[1].y, t0, t1); p1 = fmaf(vw.y, t1, vw.x * t0);
                tanh2(A[2].x, A[2].y, t0, t1); p2 = fmaf(vw.y, t1, vw.x * t0);
                tanh2(A[3].x, A[3].y, t0, t1); p3 = fmaf(vw.y, t1, vw.x * t0);
                tanh2(A[4].x, A[4].y, t0, t1); p4 = fmaf(vw.y, t1, vw.x * t0);
                tanh2(A[5].x, A[5].y, t0, t1); p5 = fmaf(vw.y, t1, vw.x * t0);
                tanh2(A[6].x, A[6].y, t0, t1); p6 = fmaf(vw.y, t1, vw.x * t0);
            }

            A[0].x = fmaf(vw.z, x03.x, A[0].x);
            A[0].y = fmaf(vw.w, x03.x, A[0].y);
            A[1].x = fmaf(vw.z, x03.y, A[1].x);
            A[1].y = fmaf(vw.w, x03.y, A[1].y);
            A[2].x = fmaf(vw.z, x03.z, A[2].x);
            A[2].y = fmaf(vw.w, x03.z, A[2].y);
            A[3].x = fmaf(vw.z, x03.w, A[3].x);
            A[3].y = fmaf(vw.w, x03.w, A[3].y);
            A[4].x = fmaf(vw.z, x47.x, A[4].x);
            A[4].y = fmaf(vw.w, x47.x, A[4].y);
            A[5].x = fmaf(vw.z, x47.y, A[5].x);
            A[5].y = fmaf(vw.w, x47.y, A[5].y);
            A[6].x = fmaf(vw.z, x47.z, A[6].x);
            A[6].y = fmaf(vw.w, x47.z, A[6].y);

            // 3 transmit-select fold levels (9 SHFLs), then 2 plain levels.
            // End state identical to round 6: every lane holds the full
            // 32-lane sum of slot 'rowmap'.
            float q01 = fold(p0, p1,   hi16, 16);
            float q23 = fold(p2, p3,   hi16, 16);
            float q45 = fold(p4, p5,   hi16, 16);
            float q67 = fold(p6, 0.0f, hi16, 16);
            float q03 = fold(q01, q23, hi8, 8);
            float q47 = fold(q45, q67, hi8, 8);
            float qq  = fold(q03, q47, hi4, 4);
            qq += __shfl_xor_sync(0xffffffffu, qq, 2);
            qq += __shfl_xor_sync(0xffffffffu, qq, 1);

            if (is_head) sp[(il * 16 + wid) * 8 + rowmap] = qq;
        }

        __syncthreads();

        // Epilogue: for each (step, row) sum the 16 warp partials.
        for (int o = t; o < CHUNK * R; o += THREADS) {
            int il = o / R, r = o % R;
            float s = 0.0f;
            #pragma unroll
            for (int wi = 0; wi < 16; wi++)
                s += sp[(il * 16 + wi) * 8 + r];
            int i = ibase + il;
            int b = b0 + r;
            if (b < BATCH) out[b * D + i] = fmaf(0.5f, s, g_bias[i]);
        }

        __syncthreads();
    }
}

// ---------------------------------------------------------------------------
extern "C" void kernel_launch(void* const* d_in, const int* in_sizes, int n_in,
                              void* d_out, int out_size) {
    const float* pixels = (const float*)d_in[0];   // [1024, 784]
    const float* W      = (const float*)d_in[1];   // [1024, 784]
    const float* c      = (const float*)d_in[2];   // [1024]
    const float* V      = (const float*)d_in[3];   // [784, 1024]
    const float* bvec   = (const float*)d_in[4];   // [784]
    float* out          = (float*)d_out;           // [1024, 784]

    cudaFuncSetAttribute(nade_main, cudaFuncAttributeMaxDynamicSharedMemorySize,
                         SMEM_BYTES);
    cudaFuncSetAttribute(nade_main, cudaFuncAttributePreferredSharedMemoryCarveout,
                         100);

    prep_kernel<<<dim3(25, 33), dim3(32, 8)>>>(W, V, bvec);
    nade_main<<<NCTAS, THREADS, SMEM_BYTES>>>(pixels, c, out);
}

// round 9
// speedup vs baseline: 1.3201x; 1.2595x over previous
#include <cuda_runtime.h>
#include <cuda_bf16.h>
#include <cstdint>

#define D 784
#define H 1024
#define BATCH 1024
#define THREADS 512
#define R 7                      // batch rows per CTA
#define NCTAS 147                // 147*7 = 1029 >= 1024
#define CHUNK 56                 // 784 = 14 * 56; 56 = 4*14 -> clean unroll 4
#define NCHUNKS (D / CHUNK)
#define SX_BYTES (D * 8 * 4)                 // sx8[D][8]
#define SP_BYTES (CHUNK * 16 * 8 * 4)        // sp[CHUNK][16][8]
#define SMEM_BYTES (SX_BYTES + SP_BYTES)     // 53760

// Scratch (no allocations allowed).
__device__ float4 g_VW[D * (H / 2)];  // g_VW[i*512 + t] = (V[i,2t], V[i,2t+1], W[2t,i], W[2t+1,i])
__device__ float  g_bias[D];          // bias[i] = b[i] + 0.5 * sum_h V[i,h]

// Two tanh evaluations in ONE MUFU op via f16x2.
__device__ __forceinline__ void tanh2(float a, float b, float& ta, float& tb) {
    uint32_t pk, tk;
    asm("cvt.rn.f16x2.f32 %0, %1, %2;" : "=r"(pk) : "f"(b), "f"(a)); // lo=a, hi=b
    asm("tanh.approx.f16x2 %0, %1;" : "=r"(tk) : "r"(pk));
    asm("{\n\t.reg .b16 l, h;\n\t"
        "mov.b32 {l, h}, %2;\n\t"
        "cvt.f32.f16 %0, l;\n\t"
        "cvt.f32.f16 %1, h;\n\t}"
        : "=f"(ta), "=f"(tb) : "r"(tk));
}

// ---------------------------------------------------------------------------
// Fused prep: blockIdx.y < 32 -> build interleaved g_VW tile (transpose W via
//                                smem tile, merge with V)
//             blockIdx.y == 32 -> bias[i] = b[i] + 0.5 * sum_h V[i,h]
// ---------------------------------------------------------------------------
__global__ void prep_kernel(const float* __restrict__ W,
                            const float* __restrict__ V,
                            const float* __restrict__ bvec) {
    if (blockIdx.y < 32) {
        __shared__ float tile[32][33];
        const int i0 = blockIdx.x * 32;
        const int h0 = blockIdx.y * 32;
        const int tx = threadIdx.x, ty = threadIdx.y;
        #pragma unroll
        for (int j = 0; j < 32; j += 8) {
            int ii = i0 + tx;
            if (ii < D) tile[ty + j][tx] = W[(h0 + ty + j) * D + ii];
        }
        __syncthreads();
        #pragma unroll
        for (int j = 0; j < 32; j += 8) {
            int i = i0 + ty + j;
            if (i < D && tx < 16) {
                int tcol = h0 / 2 + tx;
                float2 v2 = reinterpret_cast<const float2*>(V)[i * (H / 2) + tcol];
                g_VW[i * (H / 2) + tcol] =
                    make_float4(v2.x, v2.y, tile[2 * tx][i - i0], tile[2 * tx + 1][i - i0]);
            }
        }
    } else {
        int lane = threadIdx.x;
        int w    = threadIdx.y;
        #pragma unroll
        for (int k = 0; k < 4; k++) {
            int i = blockIdx.x * 32 + w * 4 + k;
            if (i >= D) continue;
            float s = 0.0f;
            #pragma unroll
            for (int j = 0; j < H / 32; j++) s += V[i * H + j * 32 + lane];
            #pragma unroll
            for (int o = 16; o > 0; o >>= 1)
                s += __shfl_xor_sync(0xffffffffu, s, o);
            if (lane == 0) g_bias[i] = bvec[i] + 0.5f * s;
        }
    }
}

// ---------------------------------------------------------------------------
// Main: one CTA per 7 batch rows; 512 threads (16 warps), 2 h per lane.
// Per step per warp: 1x LDG.128 (v+w interleaved); 2x LDS.128 xs (broadcast);
// 7 tanh2; 14 dot FMA; 14 acc FMA; round-6 16-SHFL butterfly; 1 pred STS.
// Unroll 4 -> four steps' LDGs batched for MLP. Partials deferred per chunk.
// ---------------------------------------------------------------------------
__global__ void __launch_bounds__(THREADS)
nade_main(const float* __restrict__ pixels,
          const float* __restrict__ c,
          float* __restrict__ out) {
    extern __shared__ char smem_raw[];
    float* sx8 = reinterpret_cast<float*>(smem_raw);              // [D][8]
    float* sp  = reinterpret_cast<float*>(smem_raw + SX_BYTES);   // [CHUNK][16][8]

    const int b0   = blockIdx.x * R;
    const int t    = threadIdx.x;
    const int lane = t & 31;
    const int wid  = t >> 5;

    for (int i = t; i < D; i += THREADS) {
        #pragma unroll
        for (int r = 0; r < R; r++) {
            int br = min(b0 + r, BATCH - 1);
            sx8[i * 8 + r] = 0.5f * pixels[br * D + i];
        }
        sx8[i * 8 + 7] = 0.0f;
    }

    float2 A[R];
    {
        float2 cc = reinterpret_cast<const float2*>(c)[t];
        cc.x *= 0.5f; cc.y *= 0.5f;
        #pragma unroll
        for (int r = 0; r < R; r++) A[r] = cc;
    }
    __syncthreads();

    const bool lo16 = (lane & 16) == 0;
    const bool lo8  = (lane & 8)  == 0;
    const bool lo4  = (lane & 4)  == 0;
    // Slot held by this lane after the 3 butterfly levels.
    const int rowmap = ((lane >> 4) & 1) | (((lane >> 3) & 1) << 1)
                     | (((lane >> 2) & 1) << 2);
    const bool is_head = (lane & 3) == 0;

    const float4* __restrict__ VW4 = g_VW;

    for (int ch = 0; ch < NCHUNKS; ch++) {
        const int ibase = ch * CHUNK;

        #pragma unroll 4
        for (int il = 0; il < CHUNK; il++) {
            const int i = ibase + il;
            float4 vw = VW4[i * (H / 2) + t];
            const float4* xs4 = reinterpret_cast<const float4*>(&sx8[i * 8]);
            float4 x03 = xs4[0];
            float4 x47 = xs4[1];

            float p0, p1, p2, p3, p4, p5, p6;
            {
                float t0, t1;
                tanh2(A[0].x, A[0].y, t0, t1); p0 = fmaf(vw.y, t1, vw.x * t0);
                tanh2(A[1].x, A[1].y, t0, t1); p1 = fmaf(vw.y, t1, vw.x * t0);
                tanh2(A[2].x, A[2].y, t0, t1); p2 = fmaf(vw.y, t1, vw.x * t0);
                tanh2(A[3].x, A[3].y, t0, t1); p3 = fmaf(vw.y, t1, vw.x * t0);
                tanh2(A[4].x, A[4].y, t0, t1); p4 = fmaf(vw.y, t1, vw.x * t0);
                tanh2(A[5].x, A[5].y, t0, t1); p5 = fmaf(vw.y, t1, vw.x * t0);
                tanh2(A[6].x, A[6].y, t0, t1); p6 = fmaf(vw.y, t1, vw.x * t0);
            }

            A[0].x = fmaf(vw.z, x03.x, A[0].x);
            A[0].y = fmaf(vw.w, x03.x, A[0].y);
            A[1].x = fmaf(vw.z, x03.y, A[1].x);
            A[1].y = fmaf(vw.w, x03.y, A[1].y);
            A[2].x = fmaf(vw.z, x03.z, A[2].x);
            A[2].y = fmaf(vw.w, x03.z, A[2].y);
            A[3].x = fmaf(vw.z, x03.w, A[3].x);
            A[3].y = fmaf(vw.w, x03.w, A[3].y);
            A[4].x = fmaf(vw.z, x47.x, A[4].x);
            A[4].y = fmaf(vw.w, x47.x, A[4].y);
            A[5].x = fmaf(vw.z, x47.y, A[5].x);
            A[5].y = fmaf(vw.w, x47.y, A[5].y);
            A[6].x = fmaf(vw.z, x47.z, A[6].x);
            A[6].y = fmaf(vw.w, x47.z, A[6].y);

            // Round-6 butterfly: both shuffles issued before the select.
            float e, f;
            e = __shfl_xor_sync(0xffffffffu, p0, 16);
            f = __shfl_xor_sync(0xffffffffu, p1, 16);
            float q01 = lo16 ? (p0 + e) : (p1 + f);
            e = __shfl_xor_sync(0xffffffffu, p2, 16);
            f = __shfl_xor_sync(0xffffffffu, p3, 16);
            float q23 = lo16 ? (p2 + e) : (p3 + f);
            e = __shfl_xor_sync(0xffffffffu, p4, 16);
            f = __shfl_xor_sync(0xffffffffu, p5, 16);
            float q45 = lo16 ? (p4 + e) : (p5 + f);
            e = __shfl_xor_sync(0xffffffffu, p6, 16);
            float q67 = lo16 ? (p6 + e) : 0.0f;   // slot 7 is zero

            e = __shfl_xor_sync(0xffffffffu, q01, 8);
            f = __shfl_xor_sync(0xffffffffu, q23, 8);
            float q0123 = lo8 ? (q01 + e) : (q23 + f);
            e = __shfl_xor_sync(0xffffffffu, q45, 8);
            f = __shfl_xor_sync(0xffffffffu, q67, 8);
            float q4567 = lo8 ? (q45 + e) : (q67 + f);

            e = __shfl_xor_sync(0xffffffffu, q0123, 4);
            f = __shfl_xor_sync(0xffffffffu, q4567, 4);
            float qq = lo4 ? (q0123 + e) : (q4567 + f);

            qq += __shfl_xor_sync(0xffffffffu, qq, 2);
            qq += __shfl_xor_sync(0xffffffffu, qq, 1);

            if (is_head) sp[(il * 16 + wid) * 8 + rowmap] = qq;
        }

        __syncthreads();

        // Epilogue: for each (step, row) sum the 16 warp partials.
        for (int o = t; o < CHUNK * R; o += THREADS) {
            int il = o / R, r = o % R;
            float s = 0.0f;
            #pragma unroll
            for (int wi = 0; wi < 16; wi++)
                s += sp[(il * 16 + wi) * 8 + r];
            int i = ibase + il;
            int b = b0 + r;
            if (b < BATCH) out[b * D + i] = fmaf(0.5f, s, g_bias[i]);
        }

        __syncthreads();
    }
}

// ---------------------------------------------------------------------------
extern "C" void kernel_launch(void* const* d_in, const int* in_sizes, int n_in,
                              void* d_out, int out_size) {
    const float* pixels = (const float*)d_in[0];   // [1024, 784]
    const float* W      = (const float*)d_in[1];   // [1024, 784]
    const float* c      = (const float*)d_in[2];   // [1024]
    const float* V      = (const float*)d_in[3];   // [784, 1024]
    const float* bvec   = (const float*)d_in[4];   // [784]
    float* out          = (float*)d_out;           // [1024, 784]

    cudaFuncSetAttribute(nade_main, cudaFuncAttributeMaxDynamicSharedMemorySize,
                         SMEM_BYTES);
    cudaFuncSetAttribute(nade_main, cudaFuncAttributePreferredSharedMemoryCarveout,
                         100);

    prep_kernel<<<dim3(25, 33), dim3(32, 8)>>>(W, V, bvec);
    nade_main<<<NCTAS, THREADS, SMEM_BYTES>>>(pixels, c, out);
}

// round 10
// speedup vs baseline: 1.5225x; 1.1533x over previous
#include <cuda_runtime.h>
#include <cuda_bf16.h>
#include <cstdint>

#define D 784
#define H 1024
#define BATCH 1024
#define THREADS 512
#define R 7                      // batch rows per CTA
#define NCTAS 147                // 147*7 = 1029 >= 1024
#define CHUNK 98                 // 784 = 8 * 98 (even trip count)
#define NCHUNKS (D / CHUNK)
#define SX_BYTES (D * 8 * 4)                 // sx8[D][8]
#define SP_BYTES (CHUNK * 16 * 8 * 4)        // sp[CHUNK][16][8]
#define SMEM_BYTES (SX_BYTES + SP_BYTES)     // 75264

// Scratch (no allocations allowed).
__device__ float4 g_VW[D * (H / 2)];  // g_VW[i*512 + t] = (V[i,2t], V[i,2t+1], W[2t,i], W[2t+1,i])
__device__ float  g_bias[D];          // bias[i] = b[i] + 0.5 * sum_h V[i,h]

// Two tanh evaluations in ONE MUFU op via f16x2.
__device__ __forceinline__ void tanh2(float a, float b, float& ta, float& tb) {
    uint32_t pk, tk;
    asm("cvt.rn.f16x2.f32 %0, %1, %2;" : "=r"(pk) : "f"(b), "f"(a)); // lo=a, hi=b
    asm("tanh.approx.f16x2 %0, %1;" : "=r"(tk) : "r"(pk));
    asm("{\n\t.reg .b16 l, h;\n\t"
        "mov.b32 {l, h}, %2;\n\t"
        "cvt.f32.f16 %0, l;\n\t"
        "cvt.f32.f16 %1, h;\n\t}"
        : "=f"(ta), "=f"(tb) : "r"(tk));
}

// ---------------------------------------------------------------------------
// Fused prep: blockIdx.y < 32 -> build interleaved g_VW tile (transpose W via
//                                smem tile, merge with V)
//             blockIdx.y == 32 -> bias[i] = b[i] + 0.5 * sum_h V[i,h]
// ---------------------------------------------------------------------------
__global__ void prep_kernel(const float* __restrict__ W,
                            const float* __restrict__ V,
                            const float* __restrict__ bvec) {
    if (blockIdx.y < 32) {
        __shared__ float tile[32][33];
        const int i0 = blockIdx.x * 32;
        const int h0 = blockIdx.y * 32;
        const int tx = threadIdx.x, ty = threadIdx.y;
        #pragma unroll
        for (int j = 0; j < 32; j += 8) {
            int ii = i0 + tx;
            if (ii < D) tile[ty + j][tx] = W[(h0 + ty + j) * D + ii];
        }
        __syncthreads();
        #pragma unroll
        for (int j = 0; j < 32; j += 8) {
            int i = i0 + ty + j;
            if (i < D && tx < 16) {
                int tcol = h0 / 2 + tx;
                float2 v2 = reinterpret_cast<const float2*>(V)[i * (H / 2) + tcol];
                g_VW[i * (H / 2) + tcol] =
                    make_float4(v2.x, v2.y, tile[2 * tx][i - i0], tile[2 * tx + 1][i - i0]);
            }
        }
    } else {
        int lane = threadIdx.x;
        int w    = threadIdx.y;
        #pragma unroll
        for (int k = 0; k < 4; k++) {
            int i = blockIdx.x * 32 + w * 4 + k;
            if (i >= D) continue;
            float s = 0.0f;
            #pragma unroll
            for (int j = 0; j < H / 32; j++) s += V[i * H + j * 32 + lane];
            #pragma unroll
            for (int o = 16; o > 0; o >>= 1)
                s += __shfl_xor_sync(0xffffffffu, s, o);
            if (lane == 0) g_bias[i] = bvec[i] + 0.5f * s;
        }
    }
}

// ---------------------------------------------------------------------------
// Main: one CTA per 7 batch rows; 512 threads (16 warps), 2 h per lane.
// Software-pipelined: each iteration prefetches the NEXT step's vw (LDG.128,
// L2-resident) and pixel pair (LDS.128) into registers before computing the
// current step, so the ~240-cycle L2 latency is fully overlapped.
// Reduction = round-6 butterfly (known-good scheduling shape).
// ---------------------------------------------------------------------------
__global__ void __launch_bounds__(THREADS, 1)
nade_main(const float* __restrict__ pixels,
          const float* __restrict__ c,
          float* __restrict__ out) {
    extern __shared__ char smem_raw[];
    float* sx8 = reinterpret_cast<float*>(smem_raw);              // [D][8]
    float* sp  = reinterpret_cast<float*>(smem_raw + SX_BYTES);   // [CHUNK][16][8]

    const int b0   = blockIdx.x * R;
    const int t    = threadIdx.x;
    const int lane = t & 31;
    const int wid  = t >> 5;

    for (int i = t; i < D; i += THREADS) {
        #pragma unroll
        for (int r = 0; r < R; r++) {
            int br = min(b0 + r, BATCH - 1);
            sx8[i * 8 + r] = 0.5f * pixels[br * D + i];
        }
        sx8[i * 8 + 7] = 0.0f;
    }

    float2 A[R];
    {
        float2 cc = reinterpret_cast<const float2*>(c)[t];
        cc.x *= 0.5f; cc.y *= 0.5f;
        #pragma unroll
        for (int r = 0; r < R; r++) A[r] = cc;
    }
    __syncthreads();

    const bool lo16 = (lane & 16) == 0;
    const bool lo8  = (lane & 8)  == 0;
    const bool lo4  = (lane & 4)  == 0;
    const int rowmap = ((lane >> 4) & 1) | (((lane >> 3) & 1) << 1)
                     | (((lane >> 2) & 1) << 2);
    const bool is_head = (lane & 3) == 0;

    const float4* __restrict__ VW4 = g_VW;

    // Prime the pipeline with step 0's operands.
    float4 vw  = VW4[t];
    float4 x03, x47;
    {
        const float4* xs4 = reinterpret_cast<const float4*>(&sx8[0]);
        x03 = xs4[0];
        x47 = xs4[1];
    }

    for (int ch = 0; ch < NCHUNKS; ch++) {
        const int ibase = ch * CHUNK;

        #pragma unroll 2
        for (int il = 0; il < CHUNK; il++) {
            const int i = ibase + il;
            // ---- prefetch next step's operands (fully overlapped) ----
            const int ip = (i + 1 < D) ? (i + 1) : (D - 1);
            float4 vw_n = VW4[ip * (H / 2) + t];
            const float4* xs4n = reinterpret_cast<const float4*>(&sx8[ip * 8]);
            float4 x03_n = xs4n[0];
            float4 x47_n = xs4n[1];

            // ---- compute current step ----
            float p0, p1, p2, p3, p4, p5, p6;
            {
                float t0, t1;
                tanh2(A[0].x, A[0].y, t0, t1); p0 = fmaf(vw.y, t1, vw.x * t0);
                tanh2(A[1].x, A[1].y, t0, t1); p1 = fmaf(vw.y, t1, vw.x * t0);
                tanh2(A[2].x, A[2].y, t0, t1); p2 = fmaf(vw.y, t1, vw.x * t0);
                tanh2(A[3].x, A[3].y, t0, t1); p3 = fmaf(vw.y, t1, vw.x * t0);
                tanh2(A[4].x, A[4].y, t0, t1); p4 = fmaf(vw.y, t1, vw.x * t0);
                tanh2(A[5].x, A[5].y, t0, t1); p5 = fmaf(vw.y, t1, vw.x * t0);
                tanh2(A[6].x, A[6].y, t0, t1); p6 = fmaf(vw.y, t1, vw.x * t0);
            }

            A[0].x = fmaf(vw.z, x03.x, A[0].x);
            A[0].y = fmaf(vw.w, x03.x, A[0].y);
            A[1].x = fmaf(vw.z, x03.y, A[1].x);
            A[1].y = fmaf(vw.w, x03.y, A[1].y);
            A[2].x = fmaf(vw.z, x03.z, A[2].x);
            A[2].y = fmaf(vw.w, x03.z, A[2].y);
            A[3].x = fmaf(vw.z, x03.w, A[3].x);
            A[3].y = fmaf(vw.w, x03.w, A[3].y);
            A[4].x = fmaf(vw.z, x47.x, A[4].x);
            A[4].y = fmaf(vw.w, x47.x, A[4].y);
            A[5].x = fmaf(vw.z, x47.y, A[5].x);
            A[5].y = fmaf(vw.w, x47.y, A[5].y);
            A[6].x = fmaf(vw.z, x47.z, A[6].x);
            A[6].y = fmaf(vw.w, x47.z, A[6].y);

            // Round-6 butterfly: both shuffles issued before the select.
            float e, f;
            e = __shfl_xor_sync(0xffffffffu, p0, 16);
            f = __shfl_xor_sync(0xffffffffu, p1, 16);
            float q01 = lo16 ? (p0 + e) : (p1 + f);
            e = __shfl_xor_sync(0xffffffffu, p2, 16);
            f = __shfl_xor_sync(0xffffffffu, p3, 16);
            float q23 = lo16 ? (p2 + e) : (p3 + f);
            e = __shfl_xor_sync(0xffffffffu, p4, 16);
            f = __shfl_xor_sync(0xffffffffu, p5, 16);
            float q45 = lo16 ? (p4 + e) : (p5 + f);
            e = __shfl_xor_sync(0xffffffffu, p6, 16);
            float q67 = lo16 ? (p6 + e) : 0.0f;   // slot 7 is zero

            e = __shfl_xor_sync(0xffffffffu, q01, 8);
            f = __shfl_xor_sync(0xffffffffu, q23, 8);
            float q0123 = lo8 ? (q01 + e) : (q23 + f);
            e = __shfl_xor_sync(0xffffffffu, q45, 8);
            f = __shfl_xor_sync(0xffffffffu, q67, 8);
            float q4567 = lo8 ? (q45 + e) : (q67 + f);

            e = __shfl_xor_sync(0xffffffffu, q0123, 4);
            f = __shfl_xor_sync(0xffffffffu, q4567, 4);
            float qq = lo4 ? (q0123 + e) : (q4567 + f);

            qq += __shfl_xor_sync(0xffffffffu, qq, 2);
            qq += __shfl_xor_sync(0xffffffffu, qq, 1);

            if (is_head) sp[(il * 16 + wid) * 8 + rowmap] = qq;

            // ---- rotate pipeline ----
            vw = vw_n; x03 = x03_n; x47 = x47_n;
        }

        __syncthreads();

        // Epilogue: for each (step, row) sum the 16 warp partials.
        for (int o = t; o < CHUNK * R; o += THREADS) {
            int il = o / R, r = o % R;
            float s = 0.0f;
            #pragma unroll
            for (int wi = 0; wi < 16; wi++)
                s += sp[(il * 16 + wi) * 8 + r];
            int i = ibase + il;
            int b = b0 + r;
            if (b < BATCH) out[b * D + i] = fmaf(0.5f, s, g_bias[i]);
        }

        __syncthreads();
    }
}

// ---------------------------------------------------------------------------
extern "C" void kernel_launch(void* const* d_in, const int* in_sizes, int n_in,
                              void* d_out, int out_size) {
    const float* pixels = (const float*)d_in[0];   // [1024, 784]
    const float* W      = (const float*)d_in[1];   // [1024, 784]
    const float* c      = (const float*)d_in[2];   // [1024]
    const float* V      = (const float*)d_in[3];   // [784, 1024]
    const float* bvec   = (const float*)d_in[4];   // [784]
    float* out          = (float*)d_out;           // [1024, 784]

    cudaFuncSetAttribute(nade_main, cudaFuncAttributeMaxDynamicSharedMemorySize,
                         SMEM_BYTES);
    cudaFuncSetAttribute(nade_main, cudaFuncAttributePreferredSharedMemoryCarveout,
                         100);

    prep_kernel<<<dim3(25, 33), dim3(32, 8)>>>(W, V, bvec);
    nade_main<<<NCTAS, THREADS, SMEM_BYTES>>>(pixels, c, out);
}